// round 3
// baseline (speedup 1.0000x reference)
#include <cuda_runtime.h>
#include <stdint.h>

#define NN 50000
#define NE 640000
#define D  128
#define TILE_M 64

typedef unsigned long long u64;

// Scratch (no allocations allowed)
__device__ float g_h[NN * D];      // post-GEMM features
__device__ float g_agg[NN * D];    // aggregated features (layers 1,2)
__device__ int   g_degi[NN];       // in-degree (edges only)
__device__ float g_dis[NN];        // rsqrt(deg+1)
__device__ int   g_off[NN + 1];    // CSR offsets (by col)
__device__ int   g_cur[NN];        // fill cursors
__device__ int   g_rows[NE];       // CSR: source row per incoming edge
__device__ float g_norm[NE];       // CSR: dis[row]*dis[col]
__device__ int   g_is64;

// ---------------------------------------------------------------------------
__device__ __forceinline__ u64 pack2(float lo, float hi) {
    u64 r;
    asm("mov.b64 %0, {%1, %2};" : "=l"(r) : "f"(lo), "f"(hi));
    return r;
}
__device__ __forceinline__ void fma2(u64& d, u64 a, u64 b) {
    asm("fma.rn.f32x2 %0, %1, %2, %0;" : "+l"(d) : "l"(a), "l"(b));
}

__device__ __forceinline__ int edge_at(const void* ei, int pos) {
    if (g_is64) return (int)((const long long*)ei)[pos];
    return ((const int*)ei)[pos];
}

// ---------------------------------------------------------------------------
// zero degree counters + detect int64 vs int32 edge index
__global__ void zero_deg_kernel(const void* ei) {
    int i = blockIdx.x * blockDim.x + threadIdx.x;
    if (i < NN) g_degi[i] = 0;
    if (i == 0) {
        const long long* p = (const long long*)ei;
        int ok = 1;
        #pragma unroll
        for (int k = 0; k < 8; k++) {
            long long v = p[k];
            if (v < 0 || v >= NN) ok = 0;
        }
        g_is64 = ok;
    }
}

__global__ void deg_count_kernel(const void* ei) {
    int e = blockIdx.x * blockDim.x + threadIdx.x;
    if (e >= NE) return;
    atomicAdd(&g_degi[edge_at(ei, NE + e)], 1);
}

// Single-block exclusive scan over g_degi -> g_off/g_cur; also g_dis.
__global__ void scan_kernel() {
    __shared__ int ssum[1024];
    const int CH = (NN + 1023) / 1024;  // 49
    int t = threadIdx.x;
    int start = t * CH;
    int s = 0;
    for (int i = 0; i < CH; i++) {
        int idx = start + i;
        if (idx < NN) {
            int d = g_degi[idx];
            s += d;
            g_dis[idx] = rsqrtf((float)(d + 1));
        }
    }
    ssum[t] = s;
    __syncthreads();
    for (int off = 1; off < 1024; off <<= 1) {
        int v = (t >= off) ? ssum[t - off] : 0;
        __syncthreads();
        ssum[t] += v;
        __syncthreads();
    }
    int run = (t == 0) ? 0 : ssum[t - 1];
    for (int i = 0; i < CH; i++) {
        int idx = start + i;
        if (idx < NN) {
            g_off[idx] = run;
            g_cur[idx] = run;
            run += g_degi[idx];
        }
    }
    if (t == 0) g_off[NN] = ssum[1023];
}

__global__ void fill_kernel(const void* ei) {
    int e = blockIdx.x * blockDim.x + threadIdx.x;
    if (e >= NE) return;
    int row = edge_at(ei, e);
    int col = edge_at(ei, NE + e);
    int pos = atomicAdd(&g_cur[col], 1);
    g_rows[pos] = row;
    g_norm[pos] = g_dis[row] * g_dis[col];
}

// ---------------------------------------------------------------------------
// C[n x 128] = A[n x 128] @ W[128 x 128], optional ReLU on A read.
// f32x2 packed-FMA inner loop: 16 FMA2 per thread per k.
__global__ void gemm_kernel(const float* __restrict__ Ain,
                            const float* __restrict__ W,
                            int n, int relu_in, int src_is_agg) {
    extern __shared__ float sm[];
    float* As = sm;               // 64 * 128
    float* Ws = sm + TILE_M * D;  // 128 * 128

    const float* A = src_is_agg ? g_agg : Ain;
    int tid  = threadIdx.x;
    int row0 = blockIdx.x * TILE_M;

    const float4* W4  = (const float4*)W;
    float4*       Ws4 = (float4*)Ws;
    #pragma unroll
    for (int i = 0; i < 16; i++) Ws4[tid + i * 256] = W4[tid + i * 256];

    const float4* A4  = (const float4*)A;
    float4*       As4 = (float4*)As;
    #pragma unroll
    for (int i = 0; i < 8; i++) {
        int idx = tid + i * 256;
        int r   = idx >> 5;
        int c4  = idx & 31;
        float4 v = make_float4(0.f, 0.f, 0.f, 0.f);
        if (row0 + r < n) {
            v = A4[(size_t)(row0 + r) * 32 + c4];
            if (relu_in) {
                v.x = fmaxf(v.x, 0.f); v.y = fmaxf(v.y, 0.f);
                v.z = fmaxf(v.z, 0.f); v.w = fmaxf(v.w, 0.f);
            }
        }
        As4[idx] = v;
    }
    __syncthreads();

    int ct = tid & 15;   // col group: 8 cols (4 f32x2 pairs)
    int rt = tid >> 4;   // row group: 4 rows
    int c0 = ct * 8;
    int r0 = rt * 4;

    u64 acc2[4][4];
    #pragma unroll
    for (int i = 0; i < 4; i++)
        #pragma unroll
        for (int j = 0; j < 4; j++) acc2[i][j] = 0ull;

    #pragma unroll 4
    for (int k = 0; k < D; k++) {
        float a0 = As[(r0 + 0) * D + k];
        float a1 = As[(r0 + 1) * D + k];
        float a2 = As[(r0 + 2) * D + k];
        float a3 = As[(r0 + 3) * D + k];
        u64 aa[4] = {pack2(a0, a0), pack2(a1, a1), pack2(a2, a2), pack2(a3, a3)};
        ulonglong2 wA = *(const ulonglong2*)&Ws[k * D + c0];
        ulonglong2 wB = *(const ulonglong2*)&Ws[k * D + c0 + 4];
        u64 ww[4] = {wA.x, wA.y, wB.x, wB.y};
        #pragma unroll
        for (int i = 0; i < 4; i++) {
            fma2(acc2[i][0], aa[i], ww[0]);
            fma2(acc2[i][1], aa[i], ww[1]);
            fma2(acc2[i][2], aa[i], ww[2]);
            fma2(acc2[i][3], aa[i], ww[3]);
        }
    }

    #pragma unroll
    for (int i = 0; i < 4; i++) {
        int row = row0 + r0 + i;
        if (row < n) {
            ulonglong2* dst = (ulonglong2*)&g_h[(size_t)row * D + c0];
            dst[0] = make_ulonglong2(acc2[i][0], acc2[i][1]);
            dst[1] = make_ulonglong2(acc2[i][2], acc2[i][3]);
        }
    }
}

// ---------------------------------------------------------------------------
// Gather-based aggregation: one warp per node.
__global__ void gather_kernel(const float* __restrict__ b,
                              float* __restrict__ out_ptr,
                              int use_out, int relu_out) {
    unsigned gid = blockIdx.x * blockDim.x + threadIdx.x;
    unsigned node = gid >> 5;
    if (node >= NN) return;
    int lane = threadIdx.x & 31;
    float* dst = use_out ? out_ptr : g_agg;

    const float4* h4 = (const float4*)g_h;

    float di = g_dis[node];
    float d2 = di * di;
    float4 bb = ((const float4*)b)[lane];
    float4 hs = h4[(size_t)node * 32 + lane];
    float4 acc;
    acc.x = fmaf(hs.x, d2, bb.x);
    acc.y = fmaf(hs.y, d2, bb.y);
    acc.z = fmaf(hs.z, d2, bb.z);
    acc.w = fmaf(hs.w, d2, bb.w);

    int s = g_off[node];
    int e = g_off[node + 1];
    int j = s;
    for (; j + 3 < e; j += 4) {
        int   r0 = g_rows[j],     r1 = g_rows[j + 1];
        int   r2 = g_rows[j + 2], r3 = g_rows[j + 3];
        float n0 = g_norm[j],     n1 = g_norm[j + 1];
        float n2 = g_norm[j + 2], n3 = g_norm[j + 3];
        float4 v0 = h4[(size_t)r0 * 32 + lane];
        float4 v1 = h4[(size_t)r1 * 32 + lane];
        float4 v2 = h4[(size_t)r2 * 32 + lane];
        float4 v3 = h4[(size_t)r3 * 32 + lane];
        acc.x = fmaf(v0.x, n0, acc.x); acc.y = fmaf(v0.y, n0, acc.y);
        acc.z = fmaf(v0.z, n0, acc.z); acc.w = fmaf(v0.w, n0, acc.w);
        acc.x = fmaf(v1.x, n1, acc.x); acc.y = fmaf(v1.y, n1, acc.y);
        acc.z = fmaf(v1.z, n1, acc.z); acc.w = fmaf(v1.w, n1, acc.w);
        acc.x = fmaf(v2.x, n2, acc.x); acc.y = fmaf(v2.y, n2, acc.y);
        acc.z = fmaf(v2.z, n2, acc.z); acc.w = fmaf(v2.w, n2, acc.w);
        acc.x = fmaf(v3.x, n3, acc.x); acc.y = fmaf(v3.y, n3, acc.y);
        acc.z = fmaf(v3.z, n3, acc.z); acc.w = fmaf(v3.w, n3, acc.w);
    }
    for (; j < e; j++) {
        int   r = g_rows[j];
        float nm = g_norm[j];
        float4 v = h4[(size_t)r * 32 + lane];
        acc.x = fmaf(v.x, nm, acc.x); acc.y = fmaf(v.y, nm, acc.y);
        acc.z = fmaf(v.z, nm, acc.z); acc.w = fmaf(v.w, nm, acc.w);
    }

    if (relu_out) {
        acc.x = fmaxf(acc.x, 0.f); acc.y = fmaxf(acc.y, 0.f);
        acc.z = fmaxf(acc.z, 0.f); acc.w = fmaxf(acc.w, 0.f);
    }
    ((float4*)dst)[(size_t)node * 32 + lane] = acc;
}

// ---------------------------------------------------------------------------
extern "C" void kernel_launch(void* const* d_in, const int* in_sizes, int n_in,
                              void* d_out, int out_size) {
    const float* x  = (const float*)d_in[0];
    const void*  ei = d_in[1];
    const float* W[3] = {(const float*)d_in[2], (const float*)d_in[4],
                         (const float*)d_in[6]};
    const float* b[3] = {(const float*)d_in[3], (const float*)d_in[5],
                         (const float*)d_in[7]};
    float* out = (float*)d_out;

    static bool attr_set = false;
    if (!attr_set) {
        cudaFuncSetAttribute(gemm_kernel,
                             cudaFuncAttributeMaxDynamicSharedMemorySize,
                             (TILE_M * D + D * D) * (int)sizeof(float));
        attr_set = true;
    }

    const int nodeBlocks   = (NN + 255) / 256;
    const int edgeBlocks   = (NE + 255) / 256;
    const int gemmBlocks   = (NN + TILE_M - 1) / TILE_M;
    const int gatherBlocks = (NN * 32 + 255) / 256;
    const size_t smem = (TILE_M * D + D * D) * sizeof(float);

    zero_deg_kernel<<<nodeBlocks, 256>>>(ei);
    deg_count_kernel<<<edgeBlocks, 256>>>(ei);
    scan_kernel<<<1, 1024>>>();
    fill_kernel<<<edgeBlocks, 256>>>(ei);

    for (int l = 0; l < 3; l++) {
        int relu_in    = (l > 0) ? 1 : 0;
        int src_is_agg = (l > 0) ? 1 : 0;
        int use_out    = (l == 2) ? 1 : 0;
        int relu_out   = (l == 2) ? 1 : 0;
        gemm_kernel<<<gemmBlocks, 256, smem>>>(x, W[l], NN, relu_in, src_is_agg);
        gather_kernel<<<gatherBlocks, 256>>>(b[l], out, use_out, relu_out);
    }
}